// round 12
// baseline (speedup 1.0000x reference)
#include <cuda_runtime.h>
#include <cuda_bf16.h>
#include <math.h>

#define N_NODES 50000
#define N_EDGES 300000
#define IN_DIM  128
#define OUTC    256
#define LAYERS  6
#define N_GRAPHS 256

// ------------------------- scratch (device globals) -------------------------
__device__ float d_h  [N_NODES * OUTC];        // 51.2 MB
__device__ float d_m  [N_NODES * OUTC];        // 51.2 MB
__device__ float d_agg[N_NODES * OUTC];        // 51.2 MB
__device__ float d_gi [N_NODES * 3 * OUTC];    // 153.6 MB
__device__ float d_gh [N_NODES * 3 * OUTC];    // 153.6 MB
__device__ float d_wihT[OUTC * 3 * OUTC];      // 768 KB  (256 x 768)
__device__ float d_whhT[OUTC * 3 * OUTC];
__device__ float d_gsum[N_GRAPHS * OUTC];
__device__ float d_gcnt[N_GRAPHS];

// ------------------------- helpers -------------------------
__global__ void zero_f4(float* p, int n4) {
    int i = blockIdx.x * blockDim.x + threadIdx.x;
    if (i < n4) ((float4*)p)[i] = make_float4(0.f, 0.f, 0.f, 0.f);
}

__global__ void init_h(const float* __restrict__ x) {
    int idx = blockIdx.x * blockDim.x + threadIdx.x;   // N_NODES*256
    if (idx >= N_NODES * OUTC) return;
    int node = idx >> 8, c = idx & 255;
    d_h[idx] = (c < IN_DIM) ? x[node * IN_DIM + c] : 0.f;
}

// transpose [3*OUTC, OUTC] row-major -> [OUTC, 3*OUTC]
__global__ void transpose_w(const float* __restrict__ w, float* __restrict__ wT) {
    int idx = blockIdx.x * blockDim.x + threadIdx.x;
    if (idx >= 3 * OUTC * OUTC) return;
    int r = idx / OUTC, c = idx % OUTC;   // w[r][c]
    wT[c * (3 * OUTC) + r] = w[idx];
}

// ------------------------- SGEMM: C[M,N] = A[M,K] * B[K,N] (+bias) ----------
// BM=128, BN=128, BK=8, 256 threads, 8x8 per thread.
#define BM 128
#define BN 128
#define BK 8
#define TM 8
#define TN 8
__global__ __launch_bounds__(256) void sgemm(
    const float* __restrict__ A, const float* __restrict__ B,
    const float* __restrict__ bias, float* __restrict__ C,
    int M, int N, int K)
{
    __shared__ float As[BK][BM];
    __shared__ float Bs[BK][BN];

    int tid = threadIdx.x;
    int tx = tid & 15;          // 0..15 (col group)
    int ty = tid >> 4;          // 0..15 (row group)
    int row0 = blockIdx.y * BM;
    int col0 = blockIdx.x * BN;

    float acc[TM][TN];
#pragma unroll
    for (int i = 0; i < TM; i++)
#pragma unroll
        for (int j = 0; j < TN; j++) acc[i][j] = 0.f;

    // A tile loader: 128 rows x 8 cols = 1024 floats / 256 thr = float4 each
    int aRow = tid >> 1;              // 0..127
    int aCol = (tid & 1) * 4;         // 0 or 4
    // B tile loader: 8 rows x 128 cols
    int bRow = tid >> 5;              // 0..7
    int bCol = (tid & 31) * 4;        // 0..124

    for (int k0 = 0; k0 < K; k0 += BK) {
        float4 av;
        if (row0 + aRow < M)
            av = *(const float4*)&A[(size_t)(row0 + aRow) * K + k0 + aCol];
        else
            av = make_float4(0.f, 0.f, 0.f, 0.f);
        As[aCol + 0][aRow] = av.x;
        As[aCol + 1][aRow] = av.y;
        As[aCol + 2][aRow] = av.z;
        As[aCol + 3][aRow] = av.w;

        float4 bv = *(const float4*)&B[(size_t)(k0 + bRow) * N + col0 + bCol];
        *(float4*)&Bs[bRow][bCol] = bv;

        __syncthreads();
#pragma unroll
        for (int kk = 0; kk < BK; kk++) {
            float ar[TM], br[TN];
#pragma unroll
            for (int i = 0; i < TM; i++) ar[i] = As[kk][ty * TM + i];
#pragma unroll
            for (int j = 0; j < TN; j++) br[j] = Bs[kk][tx * TN + j];
#pragma unroll
            for (int i = 0; i < TM; i++)
#pragma unroll
                for (int j = 0; j < TN; j++)
                    acc[i][j] = fmaf(ar[i], br[j], acc[i][j]);
        }
        __syncthreads();
    }

#pragma unroll
    for (int i = 0; i < TM; i++) {
        int r = row0 + ty * TM + i;
        if (r >= M) continue;
#pragma unroll
        for (int j = 0; j < TN; j += 4) {
            int c = col0 + tx * TN + j;
            float4 v = make_float4(acc[i][j], acc[i][j + 1], acc[i][j + 2], acc[i][j + 3]);
            if (bias) {
                v.x += bias[c]; v.y += bias[c + 1]; v.z += bias[c + 2]; v.w += bias[c + 3];
            }
            *(float4*)&C[(size_t)r * N + c] = v;
        }
    }
}

// ------------------------- edge scatter-add ---------------------------------
// thread t -> edge = t>>6, float4 chunk = (t&63)
__global__ void scatter_add(const int* __restrict__ src,
                            const int* __restrict__ dst)
{
    int t = blockIdx.x * blockDim.x + threadIdx.x;
    int e = t >> 6;
    if (e >= N_EDGES) return;
    int c4 = (t & 63) * 4;
    int s = src[e];
    int d = dst[e];
    float4 v = *(const float4*)&d_m[(size_t)s * OUTC + c4];
    float* o = &d_agg[(size_t)d * OUTC + c4];
    atomicAdd(o + 0, v.x);
    atomicAdd(o + 1, v.y);
    atomicAdd(o + 2, v.z);
    atomicAdd(o + 3, v.w);
}

// ------------------------- GRU elementwise (in-place h) ---------------------
__device__ __forceinline__ float sigm(float x) { return 1.f / (1.f + expf(-x)); }

__global__ void gru_elem() {
    int idx = blockIdx.x * blockDim.x + threadIdx.x;
    if (idx >= N_NODES * OUTC) return;
    int node = idx >> 8, c = idx & 255;
    const float* gi = d_gi + (size_t)node * 3 * OUTC;
    const float* gh = d_gh + (size_t)node * 3 * OUTC;
    float r  = sigm(gi[c] + gh[c]);
    float z  = sigm(gi[OUTC + c] + gh[OUTC + c]);
    float ng = tanhf(gi[2 * OUTC + c] + r * gh[2 * OUTC + c]);
    float hv = d_h[idx];
    d_h[idx] = (1.f - z) * ng + z * hv;
}

// ------------------------- mean pool -----------------------------------------
__global__ void pool_accum(const int* __restrict__ batch) {
    int t = blockIdx.x * blockDim.x + threadIdx.x;
    int node = t >> 6;
    if (node >= N_NODES) return;
    int c4 = (t & 63) * 4;
    int g = batch[node];
    float4 v = *(const float4*)&d_h[(size_t)node * OUTC + c4];
    float* o = &d_gsum[(size_t)g * OUTC + c4];
    atomicAdd(o + 0, v.x);
    atomicAdd(o + 1, v.y);
    atomicAdd(o + 2, v.z);
    atomicAdd(o + 3, v.w);
    if (c4 == 0) atomicAdd(&d_gcnt[g], 1.f);
}

// ------------------------- classifier head ----------------------------------
__global__ __launch_bounds__(128) void classify(
    const float* __restrict__ W1, const float* __restrict__ b1,
    const float* __restrict__ W2, const float* __restrict__ b2,
    float* __restrict__ out)
{
    int g = blockIdx.x;
    int j = threadIdx.x;   // 0..127
    __shared__ float gv[OUTC];
    __shared__ float red[128];
    float cnt = fmaxf(d_gcnt[g], 1.f);
    gv[j]       = d_gsum[g * OUTC + j] / cnt;
    gv[j + 128] = d_gsum[g * OUTC + j + 128] / cnt;
    __syncthreads();
    float acc = b1[j];
#pragma unroll 8
    for (int k = 0; k < OUTC; k++) acc = fmaf(gv[k], W1[j * OUTC + k], acc);
    float hc = fmaxf(acc, 0.f);
    red[j] = hc * W2[j];
    __syncthreads();
    for (int s = 64; s > 0; s >>= 1) {
        if (j < s) red[j] += red[j + s];
        __syncthreads();
    }
    if (j == 0) {
        float logit = red[0] + b2[0];
        out[g] = 1.f / (1.f + expf(-logit));
    }
}

// ------------------------- launch --------------------------------------------
extern "C" void kernel_launch(void* const* d_in, const int* in_sizes, int n_in,
                              void* d_out, int out_size)
{
    const float* x    = (const float*)d_in[0];
    const int*   eidx = (const int*)d_in[1];     // int32! (jax x64 disabled)
    const int*   batch= (const int*)d_in[2];
    const float* Wl   = (const float*)d_in[3];   // [6,256,256]
    const float* w_ih = (const float*)d_in[4];   // [768,256]
    const float* w_hh = (const float*)d_in[5];
    const float* b_ih = (const float*)d_in[6];
    const float* b_hh = (const float*)d_in[7];
    const float* W1   = (const float*)d_in[8];
    const float* b1   = (const float*)d_in[9];
    const float* W2   = (const float*)d_in[10];
    const float* b2   = (const float*)d_in[11];
    float* out = (float*)d_out;

    const int* src = eidx;
    const int* dst = eidx + N_EDGES;

    float *p_m, *p_agg, *p_h, *p_gi, *p_gh, *p_wihT, *p_whhT, *p_gsum, *p_gcnt;
    cudaGetSymbolAddress((void**)&p_m,    d_m);
    cudaGetSymbolAddress((void**)&p_agg,  d_agg);
    cudaGetSymbolAddress((void**)&p_h,    d_h);
    cudaGetSymbolAddress((void**)&p_gi,   d_gi);
    cudaGetSymbolAddress((void**)&p_gh,   d_gh);
    cudaGetSymbolAddress((void**)&p_wihT, d_wihT);
    cudaGetSymbolAddress((void**)&p_whhT, d_whhT);
    cudaGetSymbolAddress((void**)&p_gsum, d_gsum);
    cudaGetSymbolAddress((void**)&p_gcnt, d_gcnt);

    // prologue: h = pad(x), transpose GRU weights
    init_h<<<(N_NODES * OUTC + 255) / 256, 256>>>(x);
    transpose_w<<<(3 * OUTC * OUTC + 255) / 256, 256>>>(w_ih, p_wihT);
    transpose_w<<<(3 * OUTC * OUTC + 255) / 256, 256>>>(w_hh, p_whhT);

    dim3 gemm_thr(256);
    dim3 gemm_m_grid(OUTC / BN, (N_NODES + BM - 1) / BM);          // N=256
    dim3 gemm_g_grid(3 * OUTC / BN, (N_NODES + BM - 1) / BM);      // N=768

    for (int l = 0; l < LAYERS; l++) {
        // m = h @ W[l]
        sgemm<<<gemm_m_grid, gemm_thr>>>(p_h, Wl + (size_t)l * OUTC * OUTC,
                                         nullptr, p_m, N_NODES, OUTC, OUTC);
        // agg = 0
        zero_f4<<<(N_NODES * OUTC / 4 + 255) / 256, 256>>>(p_agg, N_NODES * OUTC / 4);
        // agg[dst] += m[src]
        scatter_add<<<(N_EDGES * 64 + 255) / 256, 256>>>(src, dst);
        // gi = agg @ w_ih^T + b_ih ; gh = h @ w_hh^T + b_hh
        sgemm<<<gemm_g_grid, gemm_thr>>>(p_agg, p_wihT, b_ih, p_gi,
                                         N_NODES, 3 * OUTC, OUTC);
        sgemm<<<gemm_g_grid, gemm_thr>>>(p_h, p_whhT, b_hh, p_gh,
                                         N_NODES, 3 * OUTC, OUTC);
        // h = GRU(agg, h)
        gru_elem<<<(N_NODES * OUTC + 255) / 256, 256>>>();
    }

    // mean pool
    zero_f4<<<(N_GRAPHS * OUTC / 4 + 255) / 256, 256>>>(p_gsum, N_GRAPHS * OUTC / 4);
    zero_f4<<<(N_GRAPHS / 4 + 63) / 64, 64>>>(p_gcnt, N_GRAPHS / 4);
    pool_accum<<<(N_NODES * 64 + 255) / 256, 256>>>(batch);

    // classifier
    classify<<<N_GRAPHS, 128>>>(W1, b1, W2, b2, out);
}

// round 13
// speedup vs baseline: 1.0004x; 1.0004x over previous
#include <cuda_runtime.h>
#include <cuda_bf16.h>
#include <math.h>

#define N_NODES 50000
#define N_EDGES 300000
#define IN_DIM  128
#define OUTC    256
#define LAYERS  6
#define N_GRAPHS 256

// ------------------------- scratch (device globals) -------------------------
__device__ float d_h  [N_NODES * OUTC];        // 51.2 MB
__device__ float d_m  [N_NODES * OUTC];        // 51.2 MB
__device__ float d_agg[N_NODES * OUTC];        // 51.2 MB
__device__ float d_gi [N_NODES * 3 * OUTC];    // 153.6 MB
__device__ float d_gh [N_NODES * 3 * OUTC];    // 153.6 MB
__device__ float d_wihT[OUTC * 3 * OUTC];      // 768 KB  (256 x 768)
__device__ float d_whhT[OUTC * 3 * OUTC];
__device__ float d_gsum[N_GRAPHS * OUTC];
__device__ float d_gcnt[N_GRAPHS];

// ------------------------- helpers -------------------------
__global__ void zero_f4(float* p, int n4) {
    int i = blockIdx.x * blockDim.x + threadIdx.x;
    if (i < n4) ((float4*)p)[i] = make_float4(0.f, 0.f, 0.f, 0.f);
}

__global__ void init_h(const float* __restrict__ x) {
    int idx = blockIdx.x * blockDim.x + threadIdx.x;   // N_NODES*256
    if (idx >= N_NODES * OUTC) return;
    int node = idx >> 8, c = idx & 255;
    d_h[idx] = (c < IN_DIM) ? x[node * IN_DIM + c] : 0.f;
}

// transpose [3*OUTC, OUTC] row-major -> [OUTC, 3*OUTC]
__global__ void transpose_w(const float* __restrict__ w, float* __restrict__ wT) {
    int idx = blockIdx.x * blockDim.x + threadIdx.x;
    if (idx >= 3 * OUTC * OUTC) return;
    int r = idx / OUTC, c = idx % OUTC;   // w[r][c]
    wT[c * (3 * OUTC) + r] = w[idx];
}

// ------------------------- SGEMM: C[M,N] = A[M,K] * B[K,N] (+bias) ----------
// BM=128, BN=128, BK=8, 256 threads, 8x8 per thread.
#define BM 128
#define BN 128
#define BK 8
#define TM 8
#define TN 8
__global__ __launch_bounds__(256) void sgemm(
    const float* __restrict__ A, const float* __restrict__ B,
    const float* __restrict__ bias, float* __restrict__ C,
    int M, int N, int K)
{
    __shared__ float As[BK][BM];
    __shared__ float Bs[BK][BN];

    int tid = threadIdx.x;
    int tx = tid & 15;          // 0..15 (col group)
    int ty = tid >> 4;          // 0..15 (row group)
    int row0 = blockIdx.y * BM;
    int col0 = blockIdx.x * BN;

    float acc[TM][TN];
#pragma unroll
    for (int i = 0; i < TM; i++)
#pragma unroll
        for (int j = 0; j < TN; j++) acc[i][j] = 0.f;

    // A tile loader: 128 rows x 8 cols = 1024 floats / 256 thr = float4 each
    int aRow = tid >> 1;              // 0..127
    int aCol = (tid & 1) * 4;         // 0 or 4
    // B tile loader: 8 rows x 128 cols
    int bRow = tid >> 5;              // 0..7
    int bCol = (tid & 31) * 4;        // 0..124

    for (int k0 = 0; k0 < K; k0 += BK) {
        float4 av;
        if (row0 + aRow < M)
            av = *(const float4*)&A[(size_t)(row0 + aRow) * K + k0 + aCol];
        else
            av = make_float4(0.f, 0.f, 0.f, 0.f);
        As[aCol + 0][aRow] = av.x;
        As[aCol + 1][aRow] = av.y;
        As[aCol + 2][aRow] = av.z;
        As[aCol + 3][aRow] = av.w;

        float4 bv = *(const float4*)&B[(size_t)(k0 + bRow) * N + col0 + bCol];
        *(float4*)&Bs[bRow][bCol] = bv;

        __syncthreads();
#pragma unroll
        for (int kk = 0; kk < BK; kk++) {
            float ar[TM], br[TN];
#pragma unroll
            for (int i = 0; i < TM; i++) ar[i] = As[kk][ty * TM + i];
#pragma unroll
            for (int j = 0; j < TN; j++) br[j] = Bs[kk][tx * TN + j];
#pragma unroll
            for (int i = 0; i < TM; i++)
#pragma unroll
                for (int j = 0; j < TN; j++)
                    acc[i][j] = fmaf(ar[i], br[j], acc[i][j]);
        }
        __syncthreads();
    }

#pragma unroll
    for (int i = 0; i < TM; i++) {
        int r = row0 + ty * TM + i;
        if (r >= M) continue;
#pragma unroll
        for (int j = 0; j < TN; j += 4) {
            int c = col0 + tx * TN + j;
            float4 v = make_float4(acc[i][j], acc[i][j + 1], acc[i][j + 2], acc[i][j + 3]);
            if (bias) {
                v.x += bias[c]; v.y += bias[c + 1]; v.z += bias[c + 2]; v.w += bias[c + 3];
            }
            *(float4*)&C[(size_t)r * N + c] = v;
        }
    }
}

// ------------------------- edge scatter-add ---------------------------------
// thread t -> edge = t>>6, float4 chunk = (t&63)
__global__ void scatter_add(const int* __restrict__ src,
                            const int* __restrict__ dst)
{
    int t = blockIdx.x * blockDim.x + threadIdx.x;
    int e = t >> 6;
    if (e >= N_EDGES) return;
    int c4 = (t & 63) * 4;
    int s = src[e];
    int d = dst[e];
    float4 v = *(const float4*)&d_m[(size_t)s * OUTC + c4];
    float* o = &d_agg[(size_t)d * OUTC + c4];
    atomicAdd(o + 0, v.x);
    atomicAdd(o + 1, v.y);
    atomicAdd(o + 2, v.z);
    atomicAdd(o + 3, v.w);
}

// ------------------------- GRU elementwise (in-place h) ---------------------
__device__ __forceinline__ float sigm(float x) { return 1.f / (1.f + expf(-x)); }

__global__ void gru_elem() {
    int idx = blockIdx.x * blockDim.x + threadIdx.x;
    if (idx >= N_NODES * OUTC) return;
    int node = idx >> 8, c = idx & 255;
    const float* gi = d_gi + (size_t)node * 3 * OUTC;
    const float* gh = d_gh + (size_t)node * 3 * OUTC;
    float r  = sigm(gi[c] + gh[c]);
    float z  = sigm(gi[OUTC + c] + gh[OUTC + c]);
    float ng = tanhf(gi[2 * OUTC + c] + r * gh[2 * OUTC + c]);
    float hv = d_h[idx];
    d_h[idx] = (1.f - z) * ng + z * hv;
}

// ------------------------- mean pool -----------------------------------------
__global__ void pool_accum(const int* __restrict__ batch) {
    int t = blockIdx.x * blockDim.x + threadIdx.x;
    int node = t >> 6;
    if (node >= N_NODES) return;
    int c4 = (t & 63) * 4;
    int g = batch[node];
    float4 v = *(const float4*)&d_h[(size_t)node * OUTC + c4];
    float* o = &d_gsum[(size_t)g * OUTC + c4];
    atomicAdd(o + 0, v.x);
    atomicAdd(o + 1, v.y);
    atomicAdd(o + 2, v.z);
    atomicAdd(o + 3, v.w);
    if (c4 == 0) atomicAdd(&d_gcnt[g], 1.f);
}

// ------------------------- classifier head ----------------------------------
__global__ __launch_bounds__(128) void classify(
    const float* __restrict__ W1, const float* __restrict__ b1,
    const float* __restrict__ W2, const float* __restrict__ b2,
    float* __restrict__ out)
{
    int g = blockIdx.x;
    int j = threadIdx.x;   // 0..127
    __shared__ float gv[OUTC];
    __shared__ float red[128];
    float cnt = fmaxf(d_gcnt[g], 1.f);
    gv[j]       = d_gsum[g * OUTC + j] / cnt;
    gv[j + 128] = d_gsum[g * OUTC + j + 128] / cnt;
    __syncthreads();
    float acc = b1[j];
#pragma unroll 8
    for (int k = 0; k < OUTC; k++) acc = fmaf(gv[k], W1[j * OUTC + k], acc);
    float hc = fmaxf(acc, 0.f);
    red[j] = hc * W2[j];
    __syncthreads();
    for (int s = 64; s > 0; s >>= 1) {
        if (j < s) red[j] += red[j + s];
        __syncthreads();
    }
    if (j == 0) {
        float logit = red[0] + b2[0];
        out[g] = 1.f / (1.f + expf(-logit));
    }
}

// ------------------------- launch --------------------------------------------
extern "C" void kernel_launch(void* const* d_in, const int* in_sizes, int n_in,
                              void* d_out, int out_size)
{
    const float* x    = (const float*)d_in[0];
    const int*   eidx = (const int*)d_in[1];     // int32! (jax x64 disabled)
    const int*   batch= (const int*)d_in[2];
    const float* Wl   = (const float*)d_in[3];   // [6,256,256]
    const float* w_ih = (const float*)d_in[4];   // [768,256]
    const float* w_hh = (const float*)d_in[5];
    const float* b_ih = (const float*)d_in[6];
    const float* b_hh = (const float*)d_in[7];
    const float* W1   = (const float*)d_in[8];
    const float* b1   = (const float*)d_in[9];
    const float* W2   = (const float*)d_in[10];
    const float* b2   = (const float*)d_in[11];
    float* out = (float*)d_out;

    const int* src = eidx;
    const int* dst = eidx + N_EDGES;

    float *p_m, *p_agg, *p_h, *p_gi, *p_gh, *p_wihT, *p_whhT, *p_gsum, *p_gcnt;
    cudaGetSymbolAddress((void**)&p_m,    d_m);
    cudaGetSymbolAddress((void**)&p_agg,  d_agg);
    cudaGetSymbolAddress((void**)&p_h,    d_h);
    cudaGetSymbolAddress((void**)&p_gi,   d_gi);
    cudaGetSymbolAddress((void**)&p_gh,   d_gh);
    cudaGetSymbolAddress((void**)&p_wihT, d_wihT);
    cudaGetSymbolAddress((void**)&p_whhT, d_whhT);
    cudaGetSymbolAddress((void**)&p_gsum, d_gsum);
    cudaGetSymbolAddress((void**)&p_gcnt, d_gcnt);

    // prologue: h = pad(x), transpose GRU weights
    init_h<<<(N_NODES * OUTC + 255) / 256, 256>>>(x);
    transpose_w<<<(3 * OUTC * OUTC + 255) / 256, 256>>>(w_ih, p_wihT);
    transpose_w<<<(3 * OUTC * OUTC + 255) / 256, 256>>>(w_hh, p_whhT);

    dim3 gemm_thr(256);
    dim3 gemm_m_grid(OUTC / BN, (N_NODES + BM - 1) / BM);          // N=256
    dim3 gemm_g_grid(3 * OUTC / BN, (N_NODES + BM - 1) / BM);      // N=768

    for (int l = 0; l < LAYERS; l++) {
        // m = h @ W[l]
        sgemm<<<gemm_m_grid, gemm_thr>>>(p_h, Wl + (size_t)l * OUTC * OUTC,
                                         nullptr, p_m, N_NODES, OUTC, OUTC);
        // agg = 0
        zero_f4<<<(N_NODES * OUTC / 4 + 255) / 256, 256>>>(p_agg, N_NODES * OUTC / 4);
        // agg[dst] += m[src]
        scatter_add<<<(N_EDGES * 64 + 255) / 256, 256>>>(src, dst);
        // gi = agg @ w_ih^T + b_ih ; gh = h @ w_hh^T + b_hh
        sgemm<<<gemm_g_grid, gemm_thr>>>(p_agg, p_wihT, b_ih, p_gi,
                                         N_NODES, 3 * OUTC, OUTC);
        sgemm<<<gemm_g_grid, gemm_thr>>>(p_h, p_whhT, b_hh, p_gh,
                                         N_NODES, 3 * OUTC, OUTC);
        // h = GRU(agg, h)
        gru_elem<<<(N_NODES * OUTC + 255) / 256, 256>>>();
    }

    // mean pool
    zero_f4<<<(N_GRAPHS * OUTC / 4 + 255) / 256, 256>>>(p_gsum, N_GRAPHS * OUTC / 4);
    zero_f4<<<(N_GRAPHS / 4 + 63) / 64, 64>>>(p_gcnt, N_GRAPHS / 4);
    pool_accum<<<(N_NODES * 64 + 255) / 256, 256>>>(batch);

    // classifier
    classify<<<N_GRAPHS, 128>>>(W1, b1, W2, b2, out);
}

// round 14
// speedup vs baseline: 1.0013x; 1.0009x over previous
#include <cuda_runtime.h>
#include <cuda_bf16.h>
#include <math.h>

#define N_NODES 50000
#define N_EDGES 300000
#define IN_DIM  128
#define OUTC    256
#define LAYERS  6
#define N_GRAPHS 256

// ------------------------- scratch (device globals) -------------------------
__device__ float d_h  [N_NODES * OUTC];        // 51.2 MB
__device__ float d_m  [N_NODES * OUTC];        // 51.2 MB
__device__ float d_agg[N_NODES * OUTC];        // 51.2 MB
__device__ float d_gi [N_NODES * 3 * OUTC];    // 153.6 MB
__device__ float d_gh [N_NODES * 3 * OUTC];    // 153.6 MB
__device__ float d_wihT[OUTC * 3 * OUTC];      // 768 KB  (256 x 768)
__device__ float d_whhT[OUTC * 3 * OUTC];
__device__ float d_gsum[N_GRAPHS * OUTC];
__device__ float d_gcnt[N_GRAPHS];

// ------------------------- helpers -------------------------
__global__ void zero_f4(float* p, int n4) {
    int i = blockIdx.x * blockDim.x + threadIdx.x;
    if (i < n4) ((float4*)p)[i] = make_float4(0.f, 0.f, 0.f, 0.f);
}

__global__ void init_h(const float* __restrict__ x) {
    int idx = blockIdx.x * blockDim.x + threadIdx.x;   // N_NODES*256
    if (idx >= N_NODES * OUTC) return;
    int node = idx >> 8, c = idx & 255;
    d_h[idx] = (c < IN_DIM) ? x[node * IN_DIM + c] : 0.f;
}

// transpose [3*OUTC, OUTC] row-major -> [OUTC, 3*OUTC]
__global__ void transpose_w(const float* __restrict__ w, float* __restrict__ wT) {
    int idx = blockIdx.x * blockDim.x + threadIdx.x;
    if (idx >= 3 * OUTC * OUTC) return;
    int r = idx / OUTC, c = idx % OUTC;   // w[r][c]
    wT[c * (3 * OUTC) + r] = w[idx];
}

// ------------------------- SGEMM: C[M,N] = A[M,K] * B[K,N] (+bias) ----------
// BM=128, BN=128, BK=8, 256 threads, 8x8 per thread.
#define BM 128
#define BN 128
#define BK 8
#define TM 8
#define TN 8
__global__ __launch_bounds__(256) void sgemm(
    const float* __restrict__ A, const float* __restrict__ B,
    const float* __restrict__ bias, float* __restrict__ C,
    int M, int N, int K)
{
    __shared__ float As[BK][BM];
    __shared__ float Bs[BK][BN];

    int tid = threadIdx.x;
    int tx = tid & 15;          // 0..15 (col group)
    int ty = tid >> 4;          // 0..15 (row group)
    int row0 = blockIdx.y * BM;
    int col0 = blockIdx.x * BN;

    float acc[TM][TN];
#pragma unroll
    for (int i = 0; i < TM; i++)
#pragma unroll
        for (int j = 0; j < TN; j++) acc[i][j] = 0.f;

    // A tile loader: 128 rows x 8 cols = 1024 floats / 256 thr = float4 each
    int aRow = tid >> 1;              // 0..127
    int aCol = (tid & 1) * 4;         // 0 or 4
    // B tile loader: 8 rows x 128 cols
    int bRow = tid >> 5;              // 0..7
    int bCol = (tid & 31) * 4;        // 0..124

    for (int k0 = 0; k0 < K; k0 += BK) {
        float4 av;
        if (row0 + aRow < M)
            av = *(const float4*)&A[(size_t)(row0 + aRow) * K + k0 + aCol];
        else
            av = make_float4(0.f, 0.f, 0.f, 0.f);
        As[aCol + 0][aRow] = av.x;
        As[aCol + 1][aRow] = av.y;
        As[aCol + 2][aRow] = av.z;
        As[aCol + 3][aRow] = av.w;

        float4 bv = *(const float4*)&B[(size_t)(k0 + bRow) * N + col0 + bCol];
        *(float4*)&Bs[bRow][bCol] = bv;

        __syncthreads();
#pragma unroll
        for (int kk = 0; kk < BK; kk++) {
            float ar[TM], br[TN];
#pragma unroll
            for (int i = 0; i < TM; i++) ar[i] = As[kk][ty * TM + i];
#pragma unroll
            for (int j = 0; j < TN; j++) br[j] = Bs[kk][tx * TN + j];
#pragma unroll
            for (int i = 0; i < TM; i++)
#pragma unroll
                for (int j = 0; j < TN; j++)
                    acc[i][j] = fmaf(ar[i], br[j], acc[i][j]);
        }
        __syncthreads();
    }

#pragma unroll
    for (int i = 0; i < TM; i++) {
        int r = row0 + ty * TM + i;
        if (r >= M) continue;
#pragma unroll
        for (int j = 0; j < TN; j += 4) {
            int c = col0 + tx * TN + j;
            float4 v = make_float4(acc[i][j], acc[i][j + 1], acc[i][j + 2], acc[i][j + 3]);
            if (bias) {
                v.x += bias[c]; v.y += bias[c + 1]; v.z += bias[c + 2]; v.w += bias[c + 3];
            }
            *(float4*)&C[(size_t)r * N + c] = v;
        }
    }
}

// ------------------------- edge scatter-add ---------------------------------
// thread t -> edge = t>>6, float4 chunk = (t&63)
__global__ void scatter_add(const int* __restrict__ src,
                            const int* __restrict__ dst)
{
    int t = blockIdx.x * blockDim.x + threadIdx.x;
    int e = t >> 6;
    if (e >= N_EDGES) return;
    int c4 = (t & 63) * 4;
    int s = src[e];
    int d = dst[e];
    float4 v = *(const float4*)&d_m[(size_t)s * OUTC + c4];
    float* o = &d_agg[(size_t)d * OUTC + c4];
    atomicAdd(o + 0, v.x);
    atomicAdd(o + 1, v.y);
    atomicAdd(o + 2, v.z);
    atomicAdd(o + 3, v.w);
}

// ------------------------- GRU elementwise (in-place h) ---------------------
__device__ __forceinline__ float sigm(float x) { return 1.f / (1.f + expf(-x)); }

__global__ void gru_elem() {
    int idx = blockIdx.x * blockDim.x + threadIdx.x;
    if (idx >= N_NODES * OUTC) return;
    int node = idx >> 8, c = idx & 255;
    const float* gi = d_gi + (size_t)node * 3 * OUTC;
    const float* gh = d_gh + (size_t)node * 3 * OUTC;
    float r  = sigm(gi[c] + gh[c]);
    float z  = sigm(gi[OUTC + c] + gh[OUTC + c]);
    float ng = tanhf(gi[2 * OUTC + c] + r * gh[2 * OUTC + c]);
    float hv = d_h[idx];
    d_h[idx] = (1.f - z) * ng + z * hv;
}

// ------------------------- mean pool -----------------------------------------
__global__ void pool_accum(const int* __restrict__ batch) {
    int t = blockIdx.x * blockDim.x + threadIdx.x;
    int node = t >> 6;
    if (node >= N_NODES) return;
    int c4 = (t & 63) * 4;
    int g = batch[node];
    float4 v = *(const float4*)&d_h[(size_t)node * OUTC + c4];
    float* o = &d_gsum[(size_t)g * OUTC + c4];
    atomicAdd(o + 0, v.x);
    atomicAdd(o + 1, v.y);
    atomicAdd(o + 2, v.z);
    atomicAdd(o + 3, v.w);
    if (c4 == 0) atomicAdd(&d_gcnt[g], 1.f);
}

// ------------------------- classifier head ----------------------------------
__global__ __launch_bounds__(128) void classify(
    const float* __restrict__ W1, const float* __restrict__ b1,
    const float* __restrict__ W2, const float* __restrict__ b2,
    float* __restrict__ out)
{
    int g = blockIdx.x;
    int j = threadIdx.x;   // 0..127
    __shared__ float gv[OUTC];
    __shared__ float red[128];
    float cnt = fmaxf(d_gcnt[g], 1.f);
    gv[j]       = d_gsum[g * OUTC + j] / cnt;
    gv[j + 128] = d_gsum[g * OUTC + j + 128] / cnt;
    __syncthreads();
    float acc = b1[j];
#pragma unroll 8
    for (int k = 0; k < OUTC; k++) acc = fmaf(gv[k], W1[j * OUTC + k], acc);
    float hc = fmaxf(acc, 0.f);
    red[j] = hc * W2[j];
    __syncthreads();
    for (int s = 64; s > 0; s >>= 1) {
        if (j < s) red[j] += red[j + s];
        __syncthreads();
    }
    if (j == 0) {
        float logit = red[0] + b2[0];
        out[g] = 1.f / (1.f + expf(-logit));
    }
}

// ------------------------- launch --------------------------------------------
extern "C" void kernel_launch(void* const* d_in, const int* in_sizes, int n_in,
                              void* d_out, int out_size)
{
    const float* x    = (const float*)d_in[0];
    const int*   eidx = (const int*)d_in[1];     // int32! (jax x64 disabled)
    const int*   batch= (const int*)d_in[2];
    const float* Wl   = (const float*)d_in[3];   // [6,256,256]
    const float* w_ih = (const float*)d_in[4];   // [768,256]
    const float* w_hh = (const float*)d_in[5];
    const float* b_ih = (const float*)d_in[6];
    const float* b_hh = (const float*)d_in[7];
    const float* W1   = (const float*)d_in[8];
    const float* b1   = (const float*)d_in[9];
    const float* W2   = (const float*)d_in[10];
    const float* b2   = (const float*)d_in[11];
    float* out = (float*)d_out;

    const int* src = eidx;
    const int* dst = eidx + N_EDGES;

    float *p_m, *p_agg, *p_h, *p_gi, *p_gh, *p_wihT, *p_whhT, *p_gsum, *p_gcnt;
    cudaGetSymbolAddress((void**)&p_m,    d_m);
    cudaGetSymbolAddress((void**)&p_agg,  d_agg);
    cudaGetSymbolAddress((void**)&p_h,    d_h);
    cudaGetSymbolAddress((void**)&p_gi,   d_gi);
    cudaGetSymbolAddress((void**)&p_gh,   d_gh);
    cudaGetSymbolAddress((void**)&p_wihT, d_wihT);
    cudaGetSymbolAddress((void**)&p_whhT, d_whhT);
    cudaGetSymbolAddress((void**)&p_gsum, d_gsum);
    cudaGetSymbolAddress((void**)&p_gcnt, d_gcnt);

    // prologue: h = pad(x), transpose GRU weights
    init_h<<<(N_NODES * OUTC + 255) / 256, 256>>>(x);
    transpose_w<<<(3 * OUTC * OUTC + 255) / 256, 256>>>(w_ih, p_wihT);
    transpose_w<<<(3 * OUTC * OUTC + 255) / 256, 256>>>(w_hh, p_whhT);

    dim3 gemm_thr(256);
    dim3 gemm_m_grid(OUTC / BN, (N_NODES + BM - 1) / BM);          // N=256
    dim3 gemm_g_grid(3 * OUTC / BN, (N_NODES + BM - 1) / BM);      // N=768

    for (int l = 0; l < LAYERS; l++) {
        // m = h @ W[l]
        sgemm<<<gemm_m_grid, gemm_thr>>>(p_h, Wl + (size_t)l * OUTC * OUTC,
                                         nullptr, p_m, N_NODES, OUTC, OUTC);
        // agg = 0
        zero_f4<<<(N_NODES * OUTC / 4 + 255) / 256, 256>>>(p_agg, N_NODES * OUTC / 4);
        // agg[dst] += m[src]
        scatter_add<<<(N_EDGES * 64 + 255) / 256, 256>>>(src, dst);
        // gi = agg @ w_ih^T + b_ih ; gh = h @ w_hh^T + b_hh
        sgemm<<<gemm_g_grid, gemm_thr>>>(p_agg, p_wihT, b_ih, p_gi,
                                         N_NODES, 3 * OUTC, OUTC);
        sgemm<<<gemm_g_grid, gemm_thr>>>(p_h, p_whhT, b_hh, p_gh,
                                         N_NODES, 3 * OUTC, OUTC);
        // h = GRU(agg, h)
        gru_elem<<<(N_NODES * OUTC + 255) / 256, 256>>>();
    }

    // mean pool
    zero_f4<<<(N_GRAPHS * OUTC / 4 + 255) / 256, 256>>>(p_gsum, N_GRAPHS * OUTC / 4);
    zero_f4<<<(N_GRAPHS / 4 + 63) / 64, 64>>>(p_gcnt, N_GRAPHS / 4);
    pool_accum<<<(N_NODES * 64 + 255) / 256, 256>>>(batch);

    // classifier
    classify<<<N_GRAPHS, 128>>>(W1, b1, W2, b2, out);
}